// round 7
// baseline (speedup 1.0000x reference)
#include <cuda_runtime.h>
#include <cuda_bf16.h>
#include <math.h>

#define Nn 16
#define Cc 64
#define Tt 300
#define Vv 25
#define NHh 4
#define Bb (Nn*Vv)          // 400
#define QKVO 192            // 2*DK+DV

__device__ float g_qkv[(size_t)Bb * QKVO * Tt];
__device__ float g_attn[(size_t)Bb * 64 * Tt];

// ---- packed fp32 helpers (FFMA2 / FMUL2 are PTX-only on sm_103a) ----
__device__ __forceinline__ float2 ffma2(float2 a, float2 b, float2 c) {
    unsigned long long A = *(unsigned long long*)&a;
    unsigned long long B = *(unsigned long long*)&b;
    unsigned long long C = *(unsigned long long*)&c;
    unsigned long long D;
    asm("fma.rn.f32x2 %0, %1, %2, %3;" : "=l"(D) : "l"(A), "l"(B), "l"(C));
    return *(float2*)&D;
}
__device__ __forceinline__ float2 fmul2(float2 a, float2 b) {
    unsigned long long A = *(unsigned long long*)&a;
    unsigned long long B = *(unsigned long long*)&b;
    unsigned long long D;
    asm("mul.rn.f32x2 %0, %1, %2;" : "=l"(D) : "l"(A), "l"(B));
    return *(float2*)&D;
}

// ---------------------------------------------------------------------------
// Kernel 1: fused data_bn (eval) + 1x1 qkv conv.
// Grid (b, 3 T-chunks of 100, 2 o-halves of 96). 50.7KB smem -> 4 CTAs/SM.
// ---------------------------------------------------------------------------
__global__ void __launch_bounds__(256, 4) qkv_kernel(
    const float* __restrict__ x,
    const float* __restrict__ dg, const float* __restrict__ db,
    const float* __restrict__ dm, const float* __restrict__ dv,
    const float* __restrict__ W,  const float* __restrict__ Wb)
{
    int b = blockIdx.x;
    int T0 = blockIdx.y * 100;
    int oh = blockIdx.z;           // o-half: outputs [oh*96, oh*96+96)
    int n = b / Vv, v = b - n * Vv;
    extern __shared__ float sm[];
    float* xs = sm;             // 64*100
    float* Wt = xs + 6400;      // 96*64  Wt[c*96+o] = W[(oh*96+o)*64+c]
    float* sc = Wt + 6144;      // 64
    float* bi = sc + 64;        // 64
    int tid = threadIdx.x;

    if (tid < 64) {
        int idx = tid * Vv + v;
        float s = dg[idx] * rsqrtf(dv[idx] + 1e-5f);
        sc[tid] = s;
        bi[tid] = db[idx] - dm[idx] * s;
    }
    for (int i = tid; i < 96 * 64; i += 256) {
        int c = i / 96, o = i - c * 96;
        Wt[i] = W[(oh * 96 + o) * 64 + c];
    }
    __syncthreads();

    const float* xb = x + ((size_t)n * Cc) * Tt * Vv + v;
    for (int i = tid; i < 64 * 100; i += 256) {
        int c = i / 100, tt = i - c * 100;
        xs[i] = xb[(size_t)(c * Tt + T0 + tt) * Vv] * sc[c] + bi[c];
    }
    __syncthreads();

    // 96x100 outputs in 4x4 tiles: 24*25 = 600 tiles, og fastest
    for (int tile = tid; tile < 600; tile += 256) {
        int tg = tile / 24, og = tile - tg * 24;
        int o0 = og * 4, t0 = tg * 4;
        float acc[4][4] = {};
        #pragma unroll 8
        for (int c = 0; c < 64; ++c) {
            float4 w4 = *(const float4*)(Wt + c * 96 + o0);
            float4 x4 = *(const float4*)(xs + c * 100 + t0);
            float wa[4] = {w4.x, w4.y, w4.z, w4.w};
            float xa[4] = {x4.x, x4.y, x4.z, x4.w};
            #pragma unroll
            for (int i = 0; i < 4; ++i)
                #pragma unroll
                for (int j = 0; j < 4; ++j)
                    acc[i][j] += wa[i] * xa[j];
        }
        int oglb = oh * 96 + o0;
        float* outp = g_qkv + ((size_t)b * QKVO + oglb) * Tt + T0 + t0;
        #pragma unroll
        for (int i = 0; i < 4; ++i) {
            float bias = Wb[oglb + i];
            float scale = (oglb + i < 64) ? 0.25f : 1.0f;  // q * DKH^-0.5
            float4 r;
            r.x = (acc[i][0] + bias) * scale;
            r.y = (acc[i][1] + bias) * scale;
            r.z = (acc[i][2] + bias) * scale;
            r.w = (acc[i][3] + bias) * scale;
            *(float4*)(outp + i * Tt) = r;
        }
    }
}

// ---------------------------------------------------------------------------
// Kernel 2: attention per (b,h,t-half). 67.6KB smem + reg cap 85 -> 3 CTAs/SM.
// QK+softmax: register logits, f32x2. AV: register probs, swizzled vt,
// butterfly select-merge. kr window per t-half spans only 452 m values.
// ---------------------------------------------------------------------------
#define KST 300   // ks row stride
#define RST 452   // krs row stride (t-half window + pad, mod 4 == 0)

__global__ void __launch_bounds__(256, 3) attn_kernel(const float* __restrict__ key_rel)
{
    int bh = blockIdx.x;
    int half = blockIdx.y;
    int b = bh >> 2, h = bh & 3;
    int mlo = half ? 0 : 148;          // m-window low bound for this t-half
    extern __shared__ float sm[];
    float* ks   = sm;                  // 16*300  [d][s]
    float* krs  = ks + 16 * KST;       // 16*452  [d][m-mlo]
    float* vt   = krs + 16 * RST;      // 304*16  [s][d] chunk-swizzled

    const float* base = g_qkv + (size_t)b * QKVO * Tt;
    const float* qg = base + (h * 16) * Tt;
    const float* kg = base + (64 + h * 16) * Tt;
    const float* vg = base + (128 + h * 16) * Tt;

    int tid = threadIdx.x;
    for (int i = tid; i < 1200; i += 256)
        ((float4*)ks)[i] = ((const float4*)kg)[i];
    for (int i = tid; i < 16 * RST; i += 256) {
        int d = i / RST, ml = i - d * RST;
        int mg = ml + mlo;
        krs[i] = (mg <= 598) ? key_rel[mg * 16 + d] : 0.f;
    }
    // vt tail rows (s = 300..303) zero
    for (int i = tid + 4800; i < 4864; i += 256)
        vt[i] = 0.f;
    // vt fill: vt[s][d], 16B chunk c = d>>2 swizzled by (s>>2)&3
    for (int i = tid; i < 4800; i += 256) {
        int d = i / 300, s = i - d * 300;
        int c = d >> 2, w = (s >> 2) & 3;
        vt[s * 16 + ((c ^ w) << 2) + (d & 3)] = vg[i];
    }
    __syncthreads();

    int warp = tid >> 5, lane = tid & 31;
    int lw = lane & 3;                         // vt swizzle key
    int oi = (((lane >> 4) & 1) << 1) | ((lane >> 3) & 1);
    int odp = (((lane >> 2) & 1) << 1) | ((lane >> 1) & 1);
    int odb = lane & 1;

    int gbeg = half ? 38 : 0;
    int gend = half ? 75 : 38;
    for (int g = gbeg + warp; g < gend; g += 8) {
        int t0 = g * 4;
        float2 L[3][4][2];
        bool v2 = (lane < 11);
        #pragma unroll
        for (int p = 0; p < 3; ++p) {
            float init = (p < 2 || v2) ? 0.f : -1e30f;
            #pragma unroll
            for (int i = 0; i < 4; ++i) {
                L[p][i][0] = make_float2(init, init);
                L[p][i][1] = make_float2(init, init);
            }
        }

        // ---- QK + rel ----
        #pragma unroll
        for (int d = 0; d < 16; ++d) {
            float4 q4 = __ldg((const float4*)(qg + d * 300 + t0));
            float2 qd[4] = { make_float2(q4.x, q4.x), make_float2(q4.y, q4.y),
                             make_float2(q4.z, q4.z), make_float2(q4.w, q4.w) };
            #pragma unroll
            for (int p = 0; p < 3; ++p) {
                if (p < 2 || v2) {
                    int s0 = p * 128 + lane * 4;
                    int m0l = s0 - t0 + 296 - mlo;     // >= 0, mod 4 == 0
                    float4 k4 = *(const float4*)(ks + d * KST + s0);
                    float4 ra = *(const float4*)(krs + d * RST + m0l);
                    float4 rb = *(const float4*)(krs + d * RST + m0l + 4);
                    float2 k01 = make_float2(k4.x, k4.y), k23 = make_float2(k4.z, k4.w);
                    float2 r01 = make_float2(ra.x, ra.y), r23 = make_float2(ra.z, ra.w);
                    float2 r45 = make_float2(rb.x, rb.y);
                    float2 r12 = make_float2(ra.y, ra.z);
                    float2 r34 = make_float2(ra.w, rb.x);
                    float2 r56 = make_float2(rb.y, rb.z);
                    L[p][0][0] = ffma2(qd[0], k01, L[p][0][0]); L[p][0][1] = ffma2(qd[0], k23, L[p][0][1]);
                    L[p][1][0] = ffma2(qd[1], k01, L[p][1][0]); L[p][1][1] = ffma2(qd[1], k23, L[p][1][1]);
                    L[p][2][0] = ffma2(qd[2], k01, L[p][2][0]); L[p][2][1] = ffma2(qd[2], k23, L[p][2][1]);
                    L[p][3][0] = ffma2(qd[3], k01, L[p][3][0]); L[p][3][1] = ffma2(qd[3], k23, L[p][3][1]);
                    L[p][0][0] = ffma2(qd[0], r34, L[p][0][0]); L[p][0][1] = ffma2(qd[0], r56, L[p][0][1]);
                    L[p][1][0] = ffma2(qd[1], r23, L[p][1][0]); L[p][1][1] = ffma2(qd[1], r45, L[p][1][1]);
                    L[p][2][0] = ffma2(qd[2], r12, L[p][2][0]); L[p][2][1] = ffma2(qd[2], r34, L[p][2][1]);
                    L[p][3][0] = ffma2(qd[3], r01, L[p][3][0]); L[p][3][1] = ffma2(qd[3], r23, L[p][3][1]);
                }
            }
        }

        // ---- softmax per row ----
        #pragma unroll
        for (int i = 0; i < 4; ++i) {
            float mx = -1e30f;
            #pragma unroll
            for (int p = 0; p < 3; ++p)
                #pragma unroll
                for (int jp = 0; jp < 2; ++jp)
                    mx = fmaxf(mx, fmaxf(L[p][i][jp].x, L[p][i][jp].y));
            #pragma unroll
            for (int o = 16; o > 0; o >>= 1)
                mx = fmaxf(mx, __shfl_xor_sync(0xffffffffu, mx, o));
            float s = 0.f;
            #pragma unroll
            for (int p = 0; p < 3; ++p)
                #pragma unroll
                for (int jp = 0; jp < 2; ++jp) {
                    float ex = __expf(L[p][i][jp].x - mx);
                    float ey = __expf(L[p][i][jp].y - mx);
                    L[p][i][jp] = make_float2(ex, ey);
                    s += ex + ey;
                }
            #pragma unroll
            for (int o = 16; o > 0; o >>= 1)
                s += __shfl_xor_sync(0xffffffffu, s, o);
            float inv = 1.f / s;
            float2 inv2 = make_float2(inv, inv);
            #pragma unroll
            for (int p = 0; p < 3; ++p)
                #pragma unroll
                for (int jp = 0; jp < 2; ++jp)
                    L[p][i][jp] = fmul2(L[p][i][jp], inv2);
        }

        // ---- AV: 2 sweeps of 8 d ----
        #pragma unroll
        for (int sweep = 0; sweep < 2; ++sweep) {
            float2 r[16];
            #pragma unroll
            for (int k = 0; k < 16; ++k) r[k] = make_float2(0.f, 0.f);

            #pragma unroll
            for (int p = 0; p < 3; ++p) {
                int sbase = p * 128 + lane * 4;
                if (sbase > 296) sbase = 296;     // invalid lanes: probs are 0
                #pragma unroll
                for (int j = 0; j < 4; ++j) {
                    const float* vp = vt + (sbase + j) * 16;
                    float4 va = *(const float4*)(vp + (((sweep * 2)     ^ lw) << 2));
                    float4 vb = *(const float4*)(vp + (((sweep * 2 + 1) ^ lw) << 2));
                    float2 v01 = make_float2(va.x, va.y);
                    float2 v23 = make_float2(va.z, va.w);
                    float2 v45 = make_float2(vb.x, vb.y);
                    float2 v67 = make_float2(vb.z, vb.w);
                    #pragma unroll
                    for (int i = 0; i < 4; ++i) {
                        float pij = (j & 1) ? L[p][i][j >> 1].y : L[p][i][j >> 1].x;
                        float2 pp = make_float2(pij, pij);
                        r[i * 4 + 0] = ffma2(pp, v01, r[i * 4 + 0]);
                        r[i * 4 + 1] = ffma2(pp, v23, r[i * 4 + 1]);
                        r[i * 4 + 2] = ffma2(pp, v45, r[i * 4 + 2]);
                        r[i * 4 + 3] = ffma2(pp, v67, r[i * 4 + 3]);
                    }
                }
            }

            // select-merge butterfly
            bool hi;
            hi = (lane & 16);
            #pragma unroll
            for (int k = 0; k < 8; ++k) {
                float2 keep = hi ? r[k + 8] : r[k];
                float2 send = hi ? r[k] : r[k + 8];
                keep.x += __shfl_xor_sync(0xffffffffu, send.x, 16);
                keep.y += __shfl_xor_sync(0xffffffffu, send.y, 16);
                r[k] = keep;
            }
            hi = (lane & 8);
            #pragma unroll
            for (int k = 0; k < 4; ++k) {
                float2 keep = hi ? r[k + 4] : r[k];
                float2 send = hi ? r[k] : r[k + 4];
                keep.x += __shfl_xor_sync(0xffffffffu, send.x, 8);
                keep.y += __shfl_xor_sync(0xffffffffu, send.y, 8);
                r[k] = keep;
            }
            hi = (lane & 4);
            #pragma unroll
            for (int k = 0; k < 2; ++k) {
                float2 keep = hi ? r[k + 2] : r[k];
                float2 send = hi ? r[k] : r[k + 2];
                keep.x += __shfl_xor_sync(0xffffffffu, send.x, 4);
                keep.y += __shfl_xor_sync(0xffffffffu, send.y, 4);
                r[k] = keep;
            }
            hi = (lane & 2);
            {
                float2 keep = hi ? r[1] : r[0];
                float2 send = hi ? r[0] : r[1];
                keep.x += __shfl_xor_sync(0xffffffffu, send.x, 2);
                keep.y += __shfl_xor_sync(0xffffffffu, send.y, 2);
                r[0] = keep;
            }
            {
                bool hb = (lane & 1);
                float keep = hb ? r[0].y : r[0].x;
                float send = hb ? r[0].x : r[0].y;
                float outv = keep + __shfl_xor_sync(0xffffffffu, send, 1);
                int d = sweep * 8 + odp * 2 + odb;
                g_attn[((size_t)b * 64 + h * 16 + d) * Tt + t0 + oi] = outv;
            }
        }
    }
}

// ---------------------------------------------------------------------------
// Kernel 3: head-mix projection + skip + BN + ReLU. 2 blocks per b (T split).
// ---------------------------------------------------------------------------
__global__ void __launch_bounds__(256, 4) proj_kernel(
    const float* __restrict__ Wa, const float* __restrict__ Ba,
    const float* __restrict__ bg, const float* __restrict__ bb,
    const float* __restrict__ bm, const float* __restrict__ bv,
    const float* __restrict__ x, float* __restrict__ out)
{
    int b = blockIdx.x;
    int half = blockIdx.y;
    int n = b / Vv, v = b - n * Vv;
    int T0 = half * 152;
    int TL = half ? 148 : 152;
    extern __shared__ float sm[];
    float* as = sm;            // 64*152
    float* Wt = as + 64 * 152; // 64*64
    float* s2 = Wt + 4096;     // 64
    float* b2 = s2 + 64;       // 64
    int tid = threadIdx.x;

    const float* ag = g_attn + (size_t)b * 64 * Tt;
    for (int i = tid; i < 64 * TL; i += 256) {
        int d = i / TL, tt = i - d * TL;
        as[d * 152 + tt] = ag[d * Tt + T0 + tt];
    }
    for (int i = tid; i < 4096; i += 256) {
        int d = i >> 6, o = i & 63;
        Wt[i] = Wa[o * 64 + d];
    }
    if (tid < 64) {
        float s = bg[tid] * rsqrtf(bv[tid] + 1e-5f);
        s2[tid] = s;
        b2[tid] = bb[tid] - bm[tid] * s;
    }
    __syncthreads();

    const float* xb = x + ((size_t)n * Cc) * Tt * Vv + v;
    float*       ob = out + ((size_t)n * Cc) * Tt * Vv + v;

    int tcols = TL >> 2;
    int ntile = 16 * tcols;
    for (int tile = tid; tile < ntile; tile += 256) {
        int og = tile & 15, tg = tile >> 4;
        int o0 = og * 4, t0 = tg * 4;
        float acc[4][4] = {};
        #pragma unroll 8
        for (int d = 0; d < 64; ++d) {
            float4 w4 = *(const float4*)(Wt + d * 64 + o0);
            float4 a4 = *(const float4*)(as + d * 152 + t0);
            float wa[4] = {w4.x, w4.y, w4.z, w4.w};
            float aa[4] = {a4.x, a4.y, a4.z, a4.w};
            #pragma unroll
            for (int i = 0; i < 4; ++i)
                #pragma unroll
                for (int j = 0; j < 4; ++j)
                    acc[i][j] += wa[i] * aa[j];
        }
        #pragma unroll
        for (int i = 0; i < 4; ++i) {
            int o = o0 + i;
            float bias = Ba[o];
            #pragma unroll
            for (int j = 0; j < 4; ++j) {
                int t = T0 + t0 + j;
                size_t gi = (size_t)(o * Tt + t) * Vv;
                float r = acc[i][j] + bias + xb[gi];
                r = r * s2[o] + b2[o];
                ob[gi] = fmaxf(r, 0.f);
            }
        }
    }
}

// ---------------------------------------------------------------------------
extern "C" void kernel_launch(void* const* d_in, const int* in_sizes, int n_in,
                              void* d_out, int out_size)
{
    const float* x       = (const float*)d_in[0];
    const float* dbn_g   = (const float*)d_in[1];
    const float* dbn_b   = (const float*)d_in[2];
    const float* dbn_m   = (const float*)d_in[3];
    const float* dbn_v   = (const float*)d_in[4];
    const float* qkv_w   = (const float*)d_in[5];
    const float* qkv_b   = (const float*)d_in[6];
    const float* key_rel = (const float*)d_in[7];
    const float* attn_w  = (const float*)d_in[8];
    const float* attn_b  = (const float*)d_in[9];
    const float* bn_g    = (const float*)d_in[10];
    const float* bn_b    = (const float*)d_in[11];
    const float* bn_m    = (const float*)d_in[12];
    const float* bn_v    = (const float*)d_in[13];
    float* out = (float*)d_out;

    const int SM1 = (6400 + 6144 + 128) * 4;                  // 50,688
    const int SM2 = (16 * KST + 16 * RST + 304 * 16) * 4;     // 67,584
    const int SM3 = (64 * 152 + 4096 + 128) * 4;              // 55,808

    cudaFuncSetAttribute(qkv_kernel,  cudaFuncAttributeMaxDynamicSharedMemorySize, SM1);
    cudaFuncSetAttribute(attn_kernel, cudaFuncAttributeMaxDynamicSharedMemorySize, SM2);
    cudaFuncSetAttribute(proj_kernel, cudaFuncAttributeMaxDynamicSharedMemorySize, SM3);

    qkv_kernel<<<dim3(Bb, 3, 2), 256, SM1>>>(x, dbn_g, dbn_b, dbn_m, dbn_v, qkv_w, qkv_b);
    attn_kernel<<<dim3(Bb * NHh, 2), 256, SM2>>>(key_rel);
    proj_kernel<<<dim3(Bb, 2), 256, SM3>>>(attn_w, attn_b, bn_g, bn_b, bn_m, bn_v, x, out);
}

// round 8
// speedup vs baseline: 1.0623x; 1.0623x over previous
#include <cuda_runtime.h>
#include <cuda_bf16.h>
#include <math.h>

#define Nn 16
#define Cc 64
#define Tt 300
#define Vv 25
#define NHh 4
#define Bb (Nn*Vv)          // 400
#define QKVO 192            // 2*DK+DV

__device__ float g_qkv[(size_t)Bb * QKVO * Tt];
__device__ float g_attn[(size_t)Bb * 64 * Tt];

// ---- packed fp32 helpers (FFMA2 / FMUL2 are PTX-only on sm_103a) ----
__device__ __forceinline__ float2 ffma2(float2 a, float2 b, float2 c) {
    unsigned long long A = *(unsigned long long*)&a;
    unsigned long long B = *(unsigned long long*)&b;
    unsigned long long C = *(unsigned long long*)&c;
    unsigned long long D;
    asm("fma.rn.f32x2 %0, %1, %2, %3;" : "=l"(D) : "l"(A), "l"(B), "l"(C));
    return *(float2*)&D;
}
__device__ __forceinline__ float2 fmul2(float2 a, float2 b) {
    unsigned long long A = *(unsigned long long*)&a;
    unsigned long long B = *(unsigned long long*)&b;
    unsigned long long D;
    asm("mul.rn.f32x2 %0, %1, %2;" : "=l"(D) : "l"(A), "l"(B));
    return *(float2*)&D;
}

// ---------------------------------------------------------------------------
// Kernel 1: fused data_bn (eval) + 1x1 qkv conv. 3 blocks per b (T split 100).
// (R6 version — proven fastest.)
// ---------------------------------------------------------------------------
__global__ void __launch_bounds__(256, 3) qkv_kernel(
    const float* __restrict__ x,
    const float* __restrict__ dg, const float* __restrict__ db,
    const float* __restrict__ dm, const float* __restrict__ dv,
    const float* __restrict__ W,  const float* __restrict__ Wb)
{
    int b = blockIdx.x;
    int T0 = blockIdx.y * 100;
    int n = b / Vv, v = b - n * Vv;
    extern __shared__ float sm[];
    float* xs = sm;             // 64*100
    float* Wt = xs + 6400;      // 12288  Wt[c*192+o] = W[o*64+c]
    float* sc = Wt + 12288;     // 64
    float* bi = sc + 64;        // 64
    int tid = threadIdx.x;

    if (tid < 64) {
        int idx = tid * Vv + v;
        float s = dg[idx] * rsqrtf(dv[idx] + 1e-5f);
        sc[tid] = s;
        bi[tid] = db[idx] - dm[idx] * s;
    }
    for (int i = tid; i < 192 * 64; i += 256) {
        int c = i / 192, o = i - c * 192;
        Wt[i] = W[o * 64 + c];
    }
    __syncthreads();

    const float* xb = x + ((size_t)n * Cc) * Tt * Vv + v;
    for (int i = tid; i < 64 * 100; i += 256) {
        int c = i / 100, tt = i - c * 100;
        xs[i] = xb[(size_t)(c * Tt + T0 + tt) * Vv] * sc[c] + bi[c];
    }
    __syncthreads();

    for (int tile = tid; tile < 1200; tile += 256) {
        int tg = tile / 48, og = tile - tg * 48;
        int o0 = og * 4, t0 = tg * 4;
        float acc[4][4] = {};
        #pragma unroll 8
        for (int c = 0; c < 64; ++c) {
            float4 w4 = *(const float4*)(Wt + c * 192 + o0);
            float4 x4 = *(const float4*)(xs + c * 100 + t0);
            float wa[4] = {w4.x, w4.y, w4.z, w4.w};
            float xa[4] = {x4.x, x4.y, x4.z, x4.w};
            #pragma unroll
            for (int i = 0; i < 4; ++i)
                #pragma unroll
                for (int j = 0; j < 4; ++j)
                    acc[i][j] += wa[i] * xa[j];
        }
        float* outp = g_qkv + ((size_t)b * QKVO + o0) * Tt + T0 + t0;
        #pragma unroll
        for (int i = 0; i < 4; ++i) {
            float bias = Wb[o0 + i];
            float scale = (o0 + i < 64) ? 0.25f : 1.0f;  // q * DKH^-0.5
            float4 r;
            r.x = (acc[i][0] + bias) * scale;
            r.y = (acc[i][1] + bias) * scale;
            r.z = (acc[i][2] + bias) * scale;
            r.w = (acc[i][3] + bias) * scale;
            *(float4*)(outp + i * Tt) = r;
        }
    }
}

// ---------------------------------------------------------------------------
// Kernel 2: attention per (b,h). 57.9KB smem (no ks!) -> 3 CTAs/SM.
// q,k straight from global (coalesced, L1-resident). Register logits + f32x2.
// AV: register probs, swizzled vt, 4 quarter-sweeps (16-reg acc, no spills),
// select-merge butterfly.
// ---------------------------------------------------------------------------
#define RST 600   // krs row stride

__global__ void __launch_bounds__(256, 3) attn_kernel(const float* __restrict__ key_rel)
{
    int bh = blockIdx.x;
    int b = bh >> 2, h = bh & 3;
    extern __shared__ float sm[];
    float* krs = sm;                   // 16*600  [d][m]
    float* vt  = krs + 16 * RST;       // 304*16  [s][d] chunk-swizzled

    const float* base = g_qkv + (size_t)b * QKVO * Tt;
    const float* qg = base + (h * 16) * Tt;
    const float* kg = base + (64 + h * 16) * Tt;
    const float* vg = base + (128 + h * 16) * Tt;

    int tid = threadIdx.x;
    for (int i = tid; i < 16 * RST; i += 256) {
        int d = i / RST, m = i - d * RST;
        krs[i] = (m <= 598) ? key_rel[m * 16 + d] : 0.f;
    }
    // vt tail rows (s = 300..303) zero
    for (int i = tid + 4800; i < 4864; i += 256)
        vt[i] = 0.f;
    // vt fill: vt[s][d], 16B chunk c = d>>2 swizzled by (s>>2)&3
    for (int i = tid; i < 4800; i += 256) {
        int d = i / 300, s = i - d * 300;
        int c = d >> 2, w = (s >> 2) & 3;
        vt[s * 16 + ((c ^ w) << 2) + (d & 3)] = vg[i];
    }
    __syncthreads();

    int warp = tid >> 5, lane = tid & 31;
    int lw = lane & 3;                         // vt swizzle key

    for (int g = warp; g < 75; g += 8) {
        int t0 = g * 4;
        float2 L[3][4][2];
        bool v2 = (lane < 11);
        #pragma unroll
        for (int p = 0; p < 3; ++p) {
            float init = (p < 2 || v2) ? 0.f : -1e30f;
            #pragma unroll
            for (int i = 0; i < 4; ++i) {
                L[p][i][0] = make_float2(init, init);
                L[p][i][1] = make_float2(init, init);
            }
        }

        // ---- QK + rel (q,k from global; kr from smem) ----
        #pragma unroll
        for (int d = 0; d < 16; ++d) {
            float4 q4 = __ldg((const float4*)(qg + d * 300 + t0));
            float2 qd[4] = { make_float2(q4.x, q4.x), make_float2(q4.y, q4.y),
                             make_float2(q4.z, q4.z), make_float2(q4.w, q4.w) };
            #pragma unroll
            for (int p = 0; p < 3; ++p) {
                if (p < 2 || v2) {
                    int s0 = p * 128 + lane * 4;
                    int m0 = s0 - t0 + 296;            // >= 0, mod 4 == 0
                    float4 k4 = __ldg((const float4*)(kg + d * 300 + s0));
                    float4 ra = *(const float4*)(krs + d * RST + m0);
                    float4 rb = *(const float4*)(krs + d * RST + m0 + 4);
                    float2 k01 = make_float2(k4.x, k4.y), k23 = make_float2(k4.z, k4.w);
                    float2 r01 = make_float2(ra.x, ra.y), r23 = make_float2(ra.z, ra.w);
                    float2 r45 = make_float2(rb.x, rb.y);
                    float2 r12 = make_float2(ra.y, ra.z);
                    float2 r34 = make_float2(ra.w, rb.x);
                    float2 r56 = make_float2(rb.y, rb.z);
                    L[p][0][0] = ffma2(qd[0], k01, L[p][0][0]); L[p][0][1] = ffma2(qd[0], k23, L[p][0][1]);
                    L[p][1][0] = ffma2(qd[1], k01, L[p][1][0]); L[p][1][1] = ffma2(qd[1], k23, L[p][1][1]);
                    L[p][2][0] = ffma2(qd[2], k01, L[p][2][0]); L[p][2][1] = ffma2(qd[2], k23, L[p][2][1]);
                    L[p][3][0] = ffma2(qd[3], k01, L[p][3][0]); L[p][3][1] = ffma2(qd[3], k23, L[p][3][1]);
                    L[p][0][0] = ffma2(qd[0], r34, L[p][0][0]); L[p][0][1] = ffma2(qd[0], r56, L[p][0][1]);
                    L[p][1][0] = ffma2(qd[1], r23, L[p][1][0]); L[p][1][1] = ffma2(qd[1], r45, L[p][1][1]);
                    L[p][2][0] = ffma2(qd[2], r12, L[p][2][0]); L[p][2][1] = ffma2(qd[2], r34, L[p][2][1]);
                    L[p][3][0] = ffma2(qd[3], r01, L[p][3][0]); L[p][3][1] = ffma2(qd[3], r23, L[p][3][1]);
                }
            }
        }

        // ---- softmax per row ----
        #pragma unroll
        for (int i = 0; i < 4; ++i) {
            float mx = -1e30f;
            #pragma unroll
            for (int p = 0; p < 3; ++p)
                #pragma unroll
                for (int jp = 0; jp < 2; ++jp)
                    mx = fmaxf(mx, fmaxf(L[p][i][jp].x, L[p][i][jp].y));
            #pragma unroll
            for (int o = 16; o > 0; o >>= 1)
                mx = fmaxf(mx, __shfl_xor_sync(0xffffffffu, mx, o));
            float s = 0.f;
            #pragma unroll
            for (int p = 0; p < 3; ++p)
                #pragma unroll
                for (int jp = 0; jp < 2; ++jp) {
                    float ex = __expf(L[p][i][jp].x - mx);
                    float ey = __expf(L[p][i][jp].y - mx);
                    L[p][i][jp] = make_float2(ex, ey);
                    s += ex + ey;
                }
            #pragma unroll
            for (int o = 16; o > 0; o >>= 1)
                s += __shfl_xor_sync(0xffffffffu, s, o);
            float inv = 1.f / s;
            float2 inv2 = make_float2(inv, inv);
            #pragma unroll
            for (int p = 0; p < 3; ++p)
                #pragma unroll
                for (int jp = 0; jp < 2; ++jp)
                    L[p][i][jp] = fmul2(L[p][i][jp], inv2);
        }

        // ---- AV: 4 quarter-sweeps of 4 head-dims (16-reg accumulator) ----
        #pragma unroll
        for (int ch = 0; ch < 4; ++ch) {
            float2 r[8];   // r[i*2+c2]: partial out[t0+i][ch*4 + c2*2 .. +1]
            #pragma unroll
            for (int k = 0; k < 8; ++k) r[k] = make_float2(0.f, 0.f);

            #pragma unroll
            for (int p = 0; p < 3; ++p) {
                int sbase = p * 128 + lane * 4;
                if (sbase > 296) sbase = 296;     // invalid lanes: probs are 0
                #pragma unroll
                for (int j = 0; j < 4; ++j) {
                    const float* vp = vt + (sbase + j) * 16;
                    float4 va = *(const float4*)(vp + ((ch ^ lw) << 2));
                    float2 v01 = make_float2(va.x, va.y);
                    float2 v23 = make_float2(va.z, va.w);
                    #pragma unroll
                    for (int i = 0; i < 4; ++i) {
                        float pij = (j & 1) ? L[p][i][j >> 1].y : L[p][i][j >> 1].x;
                        float2 pp = make_float2(pij, pij);
                        r[i * 2 + 0] = ffma2(pp, v01, r[i * 2 + 0]);
                        r[i * 2 + 1] = ffma2(pp, v23, r[i * 2 + 1]);
                    }
                }
            }

            // select-merge butterfly: i1 <- bit4, i0 <- bit3, c2 <- bit2, dd0 <- bit1
            bool hi;
            hi = (lane & 16);
            #pragma unroll
            for (int k = 0; k < 4; ++k) {
                float2 keep = hi ? r[k + 4] : r[k];
                float2 send = hi ? r[k] : r[k + 4];
                keep.x += __shfl_xor_sync(0xffffffffu, send.x, 16);
                keep.y += __shfl_xor_sync(0xffffffffu, send.y, 16);
                r[k] = keep;
            }
            hi = (lane & 8);
            #pragma unroll
            for (int k = 0; k < 2; ++k) {
                float2 keep = hi ? r[k + 2] : r[k];
                float2 send = hi ? r[k] : r[k + 2];
                keep.x += __shfl_xor_sync(0xffffffffu, send.x, 8);
                keep.y += __shfl_xor_sync(0xffffffffu, send.y, 8);
                r[k] = keep;
            }
            hi = (lane & 4);
            {
                float2 keep = hi ? r[1] : r[0];
                float2 send = hi ? r[0] : r[1];
                keep.x += __shfl_xor_sync(0xffffffffu, send.x, 4);
                keep.y += __shfl_xor_sync(0xffffffffu, send.y, 4);
                r[0] = keep;
            }
            {
                bool hb = (lane & 2);
                float keep = hb ? r[0].y : r[0].x;
                float send = hb ? r[0].x : r[0].y;
                float val = keep + __shfl_xor_sync(0xffffffffu, send, 2);
                val += __shfl_xor_sync(0xffffffffu, val, 1);
                if (!(lane & 1)) {
                    int i  = (((lane >> 4) & 1) << 1) | ((lane >> 3) & 1);
                    int dd = (((lane >> 2) & 1) << 1) | ((lane >> 1) & 1);
                    int d = ch * 4 + dd;
                    g_attn[((size_t)b * 64 + h * 16 + d) * Tt + t0 + i] = val;
                }
            }
        }
    }
}

// ---------------------------------------------------------------------------
// Kernel 3: head-mix projection + skip + BN + ReLU. 2 blocks per b (T split).
// (R6 version.)
// ---------------------------------------------------------------------------
__global__ void __launch_bounds__(256, 4) proj_kernel(
    const float* __restrict__ Wa, const float* __restrict__ Ba,
    const float* __restrict__ bg, const float* __restrict__ bb,
    const float* __restrict__ bm, const float* __restrict__ bv,
    const float* __restrict__ x, float* __restrict__ out)
{
    int b = blockIdx.x;
    int half = blockIdx.y;
    int n = b / Vv, v = b - n * Vv;
    int T0 = half * 152;
    int TL = half ? 148 : 152;
    extern __shared__ float sm[];
    float* as = sm;            // 64*152
    float* Wt = as + 64 * 152; // 64*64
    float* s2 = Wt + 4096;     // 64
    float* b2 = s2 + 64;       // 64
    int tid = threadIdx.x;

    const float* ag = g_attn + (size_t)b * 64 * Tt;
    for (int i = tid; i < 64 * TL; i += 256) {
        int d = i / TL, tt = i - d * TL;
        as[d * 152 + tt] = ag[d * Tt + T0 + tt];
    }
    for (int i = tid; i < 4096; i += 256) {
        int d = i >> 6, o = i & 63;
        Wt[i] = Wa[o * 64 + d];
    }
    if (tid < 64) {
        float s = bg[tid] * rsqrtf(bv[tid] + 1e-5f);
        s2[tid] = s;
        b2[tid] = bb[tid] - bm[tid] * s;
    }
    __syncthreads();

    const float* xb = x + ((size_t)n * Cc) * Tt * Vv + v;
    float*       ob = out + ((size_t)n * Cc) * Tt * Vv + v;

    int tcols = TL >> 2;
    int ntile = 16 * tcols;
    for (int tile = tid; tile < ntile; tile += 256) {
        int og = tile & 15, tg = tile >> 4;
        int o0 = og * 4, t0 = tg * 4;
        float acc[4][4] = {};
        #pragma unroll 8
        for (int d = 0; d < 64; ++d) {
            float4 w4 = *(const float4*)(Wt + d * 64 + o0);
            float4 a4 = *(const float4*)(as + d * 152 + t0);
            float wa[4] = {w4.x, w4.y, w4.z, w4.w};
            float aa[4] = {a4.x, a4.y, a4.z, a4.w};
            #pragma unroll
            for (int i = 0; i < 4; ++i)
                #pragma unroll
                for (int j = 0; j < 4; ++j)
                    acc[i][j] += wa[i] * aa[j];
        }
        #pragma unroll
        for (int i = 0; i < 4; ++i) {
            int o = o0 + i;
            float bias = Ba[o];
            #pragma unroll
            for (int j = 0; j < 4; ++j) {
                int t = T0 + t0 + j;
                size_t gi = (size_t)(o * Tt + t) * Vv;
                float r = acc[i][j] + bias + xb[gi];
                r = r * s2[o] + b2[o];
                ob[gi] = fmaxf(r, 0.f);
            }
        }
    }
}

// ---------------------------------------------------------------------------
extern "C" void kernel_launch(void* const* d_in, const int* in_sizes, int n_in,
                              void* d_out, int out_size)
{
    const float* x       = (const float*)d_in[0];
    const float* dbn_g   = (const float*)d_in[1];
    const float* dbn_b   = (const float*)d_in[2];
    const float* dbn_m   = (const float*)d_in[3];
    const float* dbn_v   = (const float*)d_in[4];
    const float* qkv_w   = (const float*)d_in[5];
    const float* qkv_b   = (const float*)d_in[6];
    const float* key_rel = (const float*)d_in[7];
    const float* attn_w  = (const float*)d_in[8];
    const float* attn_b  = (const float*)d_in[9];
    const float* bn_g    = (const float*)d_in[10];
    const float* bn_b    = (const float*)d_in[11];
    const float* bn_m    = (const float*)d_in[12];
    const float* bn_v    = (const float*)d_in[13];
    float* out = (float*)d_out;

    const int SM1 = (6400 + 12288 + 128) * 4;          // 75,264
    const int SM2 = (16 * RST + 304 * 16) * 4;         // 57,856
    const int SM3 = (64 * 152 + 4096 + 128) * 4;       // 55,808

    cudaFuncSetAttribute(qkv_kernel,  cudaFuncAttributeMaxDynamicSharedMemorySize, SM1);
    cudaFuncSetAttribute(attn_kernel, cudaFuncAttributeMaxDynamicSharedMemorySize, SM2);
    cudaFuncSetAttribute(proj_kernel, cudaFuncAttributeMaxDynamicSharedMemorySize, SM3);

    qkv_kernel<<<dim3(Bb, 3), 256, SM1>>>(x, dbn_g, dbn_b, dbn_m, dbn_v, qkv_w, qkv_b);
    attn_kernel<<<Bb * NHh, 256, SM2>>>(key_rel);
    proj_kernel<<<dim3(Bb, 2), 256, SM3>>>(attn_w, attn_b, bn_g, bn_b, bn_m, bn_v, x, out);
}

// round 9
// speedup vs baseline: 1.1515x; 1.0840x over previous
#include <cuda_runtime.h>
#include <cuda_bf16.h>
#include <math.h>

#define Nn 16
#define Cc 64
#define Tt 300
#define Vv 25
#define NHh 4
#define Bb (Nn*Vv)          // 400
#define QKVO 192            // 2*DK+DV

__device__ float g_qkv[(size_t)Bb * QKVO * Tt];
__device__ float g_attn[(size_t)Bb * 64 * Tt];

// ---- packed fp32 helpers (FFMA2 / FMUL2 are PTX-only on sm_103a) ----
__device__ __forceinline__ float2 ffma2(float2 a, float2 b, float2 c) {
    unsigned long long A = *(unsigned long long*)&a;
    unsigned long long B = *(unsigned long long*)&b;
    unsigned long long C = *(unsigned long long*)&c;
    unsigned long long D;
    asm("fma.rn.f32x2 %0, %1, %2, %3;" : "=l"(D) : "l"(A), "l"(B), "l"(C));
    return *(float2*)&D;
}
__device__ __forceinline__ float2 fmul2(float2 a, float2 b) {
    unsigned long long A = *(unsigned long long*)&a;
    unsigned long long B = *(unsigned long long*)&b;
    unsigned long long D;
    asm("mul.rn.f32x2 %0, %1, %2;" : "=l"(D) : "l"(A), "l"(B));
    return *(float2*)&D;
}

// ---------------------------------------------------------------------------
// Kernel 1: fused data_bn (eval) + 1x1 qkv conv, column-batched over (t,v).
// Grid (n, 25 t-groups of 12). Per block: 3 t-chunks x 2 o-halves.
// x reads fully coalesced; xs stored [c][v][tt] so tile columns are float4.
// ---------------------------------------------------------------------------
__global__ void __launch_bounds__(256, 3) qkv_kernel(
    const float* __restrict__ x,
    const float* __restrict__ dg, const float* __restrict__ db,
    const float* __restrict__ dm, const float* __restrict__ dv,
    const float* __restrict__ W,  const float* __restrict__ Wb)
{
    int n = blockIdx.x;
    int tgrp = blockIdx.y;           // t base = tgrp*12
    extern __shared__ float sm[];
    float* xs  = sm;                 // 64*100  [c][v*4+tt]
    float* Wt  = xs + 6400;          // 64*96   [c][o] (current o-half)
    float* scv = Wt + 6144;          // 1600    [c*25+v]
    float* biv = scv + 1600;         // 1600
    int tid = threadIdx.x;

    // dbn fold: channel index in (C*V) layout is c*25+v == i
    for (int i = tid; i < 1600; i += 256) {
        float s = dg[i] * rsqrtf(dv[i] + 1e-5f);
        scv[i] = s;
        biv[i] = db[i] - dm[i] * s;
    }
    __syncthreads();

    for (int chunk = 0; chunk < 3; ++chunk) {
        int t0 = tgrp * 12 + chunk * 4;
        // xs fill: coalesced read of x[n][c][t0..t0+3][0..24] (100 floats/c)
        for (int i = tid; i < 6400; i += 256) {
            int c = i / 100, r = i - c * 100;
            int tt = r / 25, v = r - tt * 25;
            float xv = x[((size_t)(n * 64 + c) * Tt + t0 + tt) * Vv + v];
            xs[c * 100 + v * 4 + tt] = xv * scv[c * 25 + v] + biv[c * 25 + v];
        }
        #pragma unroll
        for (int oh = 0; oh < 2; ++oh) {
            for (int i = tid; i < 6144; i += 256) {
                int c = i / 96, o = i - c * 96;
                Wt[i] = W[(oh * 96 + o) * 64 + c];
            }
            __syncthreads();

            // 600 tiles: v = tile/24, og = tile%24; 4 o x 4 tt each
            for (int tile = tid; tile < 600; tile += 256) {
                int v = tile / 24, og = tile - v * 24;
                int o0 = og * 4;
                const float* xcol = xs + v * 4;
                float acc[4][4] = {};
                #pragma unroll 8
                for (int c = 0; c < 64; ++c) {
                    float4 w4 = *(const float4*)(Wt + c * 96 + o0);
                    float4 x4 = *(const float4*)(xcol + c * 100);
                    float wa[4] = {w4.x, w4.y, w4.z, w4.w};
                    float xa[4] = {x4.x, x4.y, x4.z, x4.w};
                    #pragma unroll
                    for (int i = 0; i < 4; ++i)
                        #pragma unroll
                        for (int j = 0; j < 4; ++j)
                            acc[i][j] += wa[i] * xa[j];
                }
                int b = n * Vv + v;
                #pragma unroll
                for (int i = 0; i < 4; ++i) {
                    int o = oh * 96 + o0 + i;
                    float bias = Wb[o];
                    float scale = (o < 64) ? 0.25f : 1.0f;  // q * DKH^-0.5
                    float4 r;
                    r.x = (acc[i][0] + bias) * scale;
                    r.y = (acc[i][1] + bias) * scale;
                    r.z = (acc[i][2] + bias) * scale;
                    r.w = (acc[i][3] + bias) * scale;
                    *(float4*)(g_qkv + ((size_t)b * QKVO + o) * Tt + t0) = r;
                }
            }
            __syncthreads();   // readers done before next Wt/xs fill
        }
    }
}

// ---------------------------------------------------------------------------
// Kernel 2: attention per (b,h) — R6 version (proven fastest).
// ---------------------------------------------------------------------------
#define KST 300   // ks row stride
#define RST 600   // krs row stride

__global__ void __launch_bounds__(256, 2) attn_kernel(const float* __restrict__ key_rel)
{
    int bh = blockIdx.x;
    int b = bh >> 2, h = bh & 3;
    extern __shared__ float sm[];
    float* ks   = sm;                  // 16*300  [d][s]
    float* krs  = ks + 16 * KST;       // 16*600  [d][m]
    float* vt   = krs + 16 * RST;      // 384*16  [s][d] chunk-swizzled

    const float* base = g_qkv + (size_t)b * QKVO * Tt;
    const float* qg = base + (h * 16) * Tt;
    const float* kg = base + (64 + h * 16) * Tt;
    const float* vg = base + (128 + h * 16) * Tt;

    int tid = threadIdx.x;
    for (int i = tid; i < 1200; i += 256)
        ((float4*)ks)[i] = ((const float4*)kg)[i];
    for (int i = tid; i < 599 * 16; i += 256) {
        int m = i >> 4, d = i & 15;
        krs[d * RST + m] = key_rel[i];
    }
    for (int i = tid + 4800; i < 6144; i += 256)
        vt[i] = 0.f;
    for (int i = tid; i < 4800; i += 256) {
        int d = i / 300, s = i - d * 300;
        int c = d >> 2, w = (s >> 2) & 3;
        vt[s * 16 + ((c ^ w) << 2) + (d & 3)] = vg[i];
    }
    __syncthreads();

    int warp = tid >> 5, lane = tid & 31;
    int lw = lane & 3;
    int oi = (((lane >> 4) & 1) << 1) | ((lane >> 3) & 1);
    int odp = (((lane >> 2) & 1) << 1) | ((lane >> 1) & 1);
    int odb = lane & 1;

    for (int g = warp; g < 75; g += 8) {
        int t0 = g * 4;
        float2 L[3][4][2];
        bool v2 = (lane < 11);
        #pragma unroll
        for (int p = 0; p < 3; ++p) {
            float init = (p < 2 || v2) ? 0.f : -1e30f;
            #pragma unroll
            for (int i = 0; i < 4; ++i) {
                L[p][i][0] = make_float2(init, init);
                L[p][i][1] = make_float2(init, init);
            }
        }

        #pragma unroll
        for (int d = 0; d < 16; ++d) {
            float4 q4 = __ldg((const float4*)(qg + d * 300 + t0));
            float2 qd[4] = { make_float2(q4.x, q4.x), make_float2(q4.y, q4.y),
                             make_float2(q4.z, q4.z), make_float2(q4.w, q4.w) };
            #pragma unroll
            for (int p = 0; p < 3; ++p) {
                if (p < 2 || v2) {
                    int s0 = p * 128 + lane * 4;
                    int m0 = s0 - t0 + 296;
                    float4 k4 = *(const float4*)(ks + d * KST + s0);
                    float4 ra = *(const float4*)(krs + d * RST + m0);
                    float4 rb = *(const float4*)(krs + d * RST + m0 + 4);
                    float2 k01 = make_float2(k4.x, k4.y), k23 = make_float2(k4.z, k4.w);
                    float2 r01 = make_float2(ra.x, ra.y), r23 = make_float2(ra.z, ra.w);
                    float2 r45 = make_float2(rb.x, rb.y);
                    float2 r12 = make_float2(ra.y, ra.z);
                    float2 r34 = make_float2(ra.w, rb.x);
                    float2 r56 = make_float2(rb.y, rb.z);
                    L[p][0][0] = ffma2(qd[0], k01, L[p][0][0]); L[p][0][1] = ffma2(qd[0], k23, L[p][0][1]);
                    L[p][1][0] = ffma2(qd[1], k01, L[p][1][0]); L[p][1][1] = ffma2(qd[1], k23, L[p][1][1]);
                    L[p][2][0] = ffma2(qd[2], k01, L[p][2][0]); L[p][2][1] = ffma2(qd[2], k23, L[p][2][1]);
                    L[p][3][0] = ffma2(qd[3], k01, L[p][3][0]); L[p][3][1] = ffma2(qd[3], k23, L[p][3][1]);
                    L[p][0][0] = ffma2(qd[0], r34, L[p][0][0]); L[p][0][1] = ffma2(qd[0], r56, L[p][0][1]);
                    L[p][1][0] = ffma2(qd[1], r23, L[p][1][0]); L[p][1][1] = ffma2(qd[1], r45, L[p][1][1]);
                    L[p][2][0] = ffma2(qd[2], r12, L[p][2][0]); L[p][2][1] = ffma2(qd[2], r34, L[p][2][1]);
                    L[p][3][0] = ffma2(qd[3], r01, L[p][3][0]); L[p][3][1] = ffma2(qd[3], r23, L[p][3][1]);
                }
            }
        }

        #pragma unroll
        for (int i = 0; i < 4; ++i) {
            float mx = -1e30f;
            #pragma unroll
            for (int p = 0; p < 3; ++p)
                #pragma unroll
                for (int jp = 0; jp < 2; ++jp)
                    mx = fmaxf(mx, fmaxf(L[p][i][jp].x, L[p][i][jp].y));
            #pragma unroll
            for (int o = 16; o > 0; o >>= 1)
                mx = fmaxf(mx, __shfl_xor_sync(0xffffffffu, mx, o));
            float s = 0.f;
            #pragma unroll
            for (int p = 0; p < 3; ++p)
                #pragma unroll
                for (int jp = 0; jp < 2; ++jp) {
                    float ex = __expf(L[p][i][jp].x - mx);
                    float ey = __expf(L[p][i][jp].y - mx);
                    L[p][i][jp] = make_float2(ex, ey);
                    s += ex + ey;
                }
            #pragma unroll
            for (int o = 16; o > 0; o >>= 1)
                s += __shfl_xor_sync(0xffffffffu, s, o);
            float inv = 1.f / s;
            float2 inv2 = make_float2(inv, inv);
            #pragma unroll
            for (int p = 0; p < 3; ++p)
                #pragma unroll
                for (int jp = 0; jp < 2; ++jp)
                    L[p][i][jp] = fmul2(L[p][i][jp], inv2);
        }

        #pragma unroll
        for (int sweep = 0; sweep < 2; ++sweep) {
            float2 r[16];
            #pragma unroll
            for (int k = 0; k < 16; ++k) r[k] = make_float2(0.f, 0.f);

            #pragma unroll
            for (int p = 0; p < 3; ++p) {
                int sbase = p * 128 + lane * 4;
                #pragma unroll
                for (int j = 0; j < 4; ++j) {
                    const float* vp = vt + (sbase + j) * 16;
                    float4 va = *(const float4*)(vp + (((sweep * 2)     ^ lw) << 2));
                    float4 vb = *(const float4*)(vp + (((sweep * 2 + 1) ^ lw) << 2));
                    float2 v01 = make_float2(va.x, va.y);
                    float2 v23 = make_float2(va.z, va.w);
                    float2 v45 = make_float2(vb.x, vb.y);
                    float2 v67 = make_float2(vb.z, vb.w);
                    #pragma unroll
                    for (int i = 0; i < 4; ++i) {
                        float pij = (j & 1) ? L[p][i][j >> 1].y : L[p][i][j >> 1].x;
                        float2 pp = make_float2(pij, pij);
                        r[i * 4 + 0] = ffma2(pp, v01, r[i * 4 + 0]);
                        r[i * 4 + 1] = ffma2(pp, v23, r[i * 4 + 1]);
                        r[i * 4 + 2] = ffma2(pp, v45, r[i * 4 + 2]);
                        r[i * 4 + 3] = ffma2(pp, v67, r[i * 4 + 3]);
                    }
                }
            }

            bool hi;
            hi = (lane & 16);
            #pragma unroll
            for (int k = 0; k < 8; ++k) {
                float2 keep = hi ? r[k + 8] : r[k];
                float2 send = hi ? r[k] : r[k + 8];
                keep.x += __shfl_xor_sync(0xffffffffu, send.x, 16);
                keep.y += __shfl_xor_sync(0xffffffffu, send.y, 16);
                r[k] = keep;
            }
            hi = (lane & 8);
            #pragma unroll
            for (int k = 0; k < 4; ++k) {
                float2 keep = hi ? r[k + 4] : r[k];
                float2 send = hi ? r[k] : r[k + 4];
                keep.x += __shfl_xor_sync(0xffffffffu, send.x, 8);
                keep.y += __shfl_xor_sync(0xffffffffu, send.y, 8);
                r[k] = keep;
            }
            hi = (lane & 4);
            #pragma unroll
            for (int k = 0; k < 2; ++k) {
                float2 keep = hi ? r[k + 2] : r[k];
                float2 send = hi ? r[k] : r[k + 2];
                keep.x += __shfl_xor_sync(0xffffffffu, send.x, 4);
                keep.y += __shfl_xor_sync(0xffffffffu, send.y, 4);
                r[k] = keep;
            }
            hi = (lane & 2);
            {
                float2 keep = hi ? r[1] : r[0];
                float2 send = hi ? r[0] : r[1];
                keep.x += __shfl_xor_sync(0xffffffffu, send.x, 2);
                keep.y += __shfl_xor_sync(0xffffffffu, send.y, 2);
                r[0] = keep;
            }
            {
                bool hb = (lane & 1);
                float keep = hb ? r[0].y : r[0].x;
                float send = hb ? r[0].x : r[0].y;
                float outv = keep + __shfl_xor_sync(0xffffffffu, send, 1);
                int d = sweep * 8 + odp * 2 + odb;
                g_attn[((size_t)b * 64 + h * 16 + d) * Tt + t0 + oi] = outv;
            }
        }
    }
}

// ---------------------------------------------------------------------------
// Kernel 3: head-mix projection + skip + BN + ReLU — R6 version.
// ---------------------------------------------------------------------------
__global__ void __launch_bounds__(256, 4) proj_kernel(
    const float* __restrict__ Wa, const float* __restrict__ Ba,
    const float* __restrict__ bg, const float* __restrict__ bb,
    const float* __restrict__ bm, const float* __restrict__ bv,
    const float* __restrict__ x, float* __restrict__ out)
{
    int b = blockIdx.x;
    int half = blockIdx.y;
    int n = b / Vv, v = b - n * Vv;
    int T0 = half * 152;
    int TL = half ? 148 : 152;
    extern __shared__ float sm[];
    float* as = sm;            // 64*152
    float* Wt = as + 64 * 152; // 64*64
    float* s2 = Wt + 4096;     // 64
    float* b2 = s2 + 64;       // 64
    int tid = threadIdx.x;

    const float* ag = g_attn + (size_t)b * 64 * Tt;
    for (int i = tid; i < 64 * TL; i += 256) {
        int d = i / TL, tt = i - d * TL;
        as[d * 152 + tt] = ag[d * Tt + T0 + tt];
    }
    for (int i = tid; i < 4096; i += 256) {
        int d = i >> 6, o = i & 63;
        Wt[i] = Wa[o * 64 + d];
    }
    if (tid < 64) {
        float s = bg[tid] * rsqrtf(bv[tid] + 1e-5f);
        s2[tid] = s;
        b2[tid] = bb[tid] - bm[tid] * s;
    }
    __syncthreads();

    const float* xb = x + ((size_t)n * Cc) * Tt * Vv + v;
    float*       ob = out + ((size_t)n * Cc) * Tt * Vv + v;

    int tcols = TL >> 2;
    int ntile = 16 * tcols;
    for (int tile = tid; tile < ntile; tile += 256) {
        int og = tile & 15, tg = tile >> 4;
        int o0 = og * 4, t0 = tg * 4;
        float acc[4][4] = {};
        #pragma unroll 8
        for (int d = 0; d < 64; ++d) {
            float4 w4 = *(const float4*)(Wt + d * 64 + o0);
            float4 a4 = *(const float4*)(as + d * 152 + t0);
            float wa[4] = {w4.x, w4.y, w4.z, w4.w};
            float aa[4] = {a4.x, a4.y, a4.z, a4.w};
            #pragma unroll
            for (int i = 0; i < 4; ++i)
                #pragma unroll
                for (int j = 0; j < 4; ++j)
                    acc[i][j] += wa[i] * aa[j];
        }
        #pragma unroll
        for (int i = 0; i < 4; ++i) {
            int o = o0 + i;
            float bias = Ba[o];
            #pragma unroll
            for (int j = 0; j < 4; ++j) {
                int t = T0 + t0 + j;
                size_t gi = (size_t)(o * Tt + t) * Vv;
                float r = acc[i][j] + bias + xb[gi];
                r = r * s2[o] + b2[o];
                ob[gi] = fmaxf(r, 0.f);
            }
        }
    }
}

// ---------------------------------------------------------------------------
extern "C" void kernel_launch(void* const* d_in, const int* in_sizes, int n_in,
                              void* d_out, int out_size)
{
    const float* x       = (const float*)d_in[0];
    const float* dbn_g   = (const float*)d_in[1];
    const float* dbn_b   = (const float*)d_in[2];
    const float* dbn_m   = (const float*)d_in[3];
    const float* dbn_v   = (const float*)d_in[4];
    const float* qkv_w   = (const float*)d_in[5];
    const float* qkv_b   = (const float*)d_in[6];
    const float* key_rel = (const float*)d_in[7];
    const float* attn_w  = (const float*)d_in[8];
    const float* attn_b  = (const float*)d_in[9];
    const float* bn_g    = (const float*)d_in[10];
    const float* bn_b    = (const float*)d_in[11];
    const float* bn_m    = (const float*)d_in[12];
    const float* bn_v    = (const float*)d_in[13];
    float* out = (float*)d_out;

    const int SM1 = (6400 + 6144 + 1600 + 1600) * 4;   // 62,976
    const int SM2 = (16 * KST + 16 * RST + 384 * 16) * 4; // 82,176
    const int SM3 = (64 * 152 + 4096 + 128) * 4;       // 55,808

    cudaFuncSetAttribute(qkv_kernel,  cudaFuncAttributeMaxDynamicSharedMemorySize, SM1);
    cudaFuncSetAttribute(attn_kernel, cudaFuncAttributeMaxDynamicSharedMemorySize, SM2);
    cudaFuncSetAttribute(proj_kernel, cudaFuncAttributeMaxDynamicSharedMemorySize, SM3);

    qkv_kernel<<<dim3(Nn, 25), 256, SM1>>>(x, dbn_g, dbn_b, dbn_m, dbn_v, qkv_w, qkv_b);
    attn_kernel<<<Bb * NHh, 256, SM2>>>(key_rel);
    proj_kernel<<<dim3(Bb, 2), 256, SM3>>>(attn_w, attn_b, bn_g, bn_b, bn_m, bn_v, x, out);
}